// round 9
// baseline (speedup 1.0000x reference)
#include <cuda_runtime.h>
#include <math.h>
#include <stdint.h>

#define BS 32
#define NQ 900
#define NC 91
#define NT 30
#define NTT (BS * NT)   // 960
#define QPB 32
#define QCHUNKS 29
#define KLOC 29
#define PITCH 901       // smem slice pitch (gcd(901,32)=1 -> conflict-free)
#define FINF 3.0e38f

__device__ __forceinline__ unsigned fkey(float f) {
    unsigned b = __float_as_uint(f);
    return (b & 0x80000000u) ? ~b : (b | 0x80000000u);
}
__device__ __forceinline__ float funkey(unsigned k) {
    unsigned b = (k & 0x80000000u) ? (k & 0x7FFFFFFFu) : ~k;
    return __uint_as_float(b);
}

__device__ __forceinline__ void wargmin(unsigned long long best, float* val, int* idx) {
    unsigned key  = (unsigned)(best >> 32);
    unsigned wmin = __reduce_min_sync(0xffffffffu, key);
    unsigned cand = (key == wmin) ? (unsigned)(best & 0xFFFFFFFFu) : 0xFFFFFFFFu;
    unsigned widx = __reduce_min_sync(0xffffffffu, cand);
    *val = funkey(wmin);
    *idx = (int)widx;
}

__device__ __forceinline__ float cost_elem(
    float4 pa, float4 pbx, float parea, float prob,
    float4 tr, float tX0, float tY0, float tX1, float tY1, float tarea)
{
    float cb = fabsf(pa.x - tr.x) + fabsf(pa.y - tr.y)
             + fabsf(pa.z - tr.z) + fabsf(pa.w - tr.w);
    float iw = fmaxf(fminf(pbx.z, tX1) - fmaxf(pbx.x, tX0), 0.f);
    float ih = fmaxf(fminf(pbx.w, tY1) - fmaxf(pbx.y, tY0), 0.f);
    float inter = iw * ih;
    float uni = parea + tarea - inter;
    float ew = fmaxf(pbx.z, tX1) - fminf(pbx.x, tX0);
    float eh = fmaxf(pbx.w, tY1) - fminf(pbx.y, tY0);
    float encl = ew * eh;
    float num = 2.0f * fmaf(inter, encl, uni * uni);
    return fmaf(5.0f, cb, 5.0f) - prob - __fdividef(num, uni * encl);
}

// ---------------------------------------------------------------------------
// Kernel 1: full cost matrix (unchanged from R8; proven). Lane owns 4
// targets (STG.128 streaming), warp 7 covers the 64-target tail.
// ---------------------------------------------------------------------------
__global__ void __launch_bounds__(256) cost_kernel(
    const float* __restrict__ logits,
    const float* __restrict__ pboxes,
    const int*   __restrict__ tlabels,
    const float* __restrict__ tboxes,
    float* __restrict__ out)
{
    __shared__ float  s_prob[QPB][92];
    __shared__ float4 s_pba[QPB];
    __shared__ float4 s_pbb[QPB];
    __shared__ float  s_parea[QPB];

    const int b     = blockIdx.y;
    const int qbase = blockIdx.x * QPB;
    const int tid   = threadIdx.x;
    const int warp  = tid >> 5;
    const int lane  = tid & 31;
    const int qlim  = min(QPB, NQ - qbase);

    for (int qi = warp; qi < qlim; qi += 8) {
        const float* lg = logits + ((size_t)b * NQ + qbase + qi) * NC;
        float x0 = (lane      < NC) ? lg[lane]      : -FINF;
        float x1 = (lane + 32 < NC) ? lg[lane + 32] : -FINF;
        float x2 = (lane + 64 < NC) ? lg[lane + 64] : -FINF;
        float m = fmaxf(x0, fmaxf(x1, x2));
        #pragma unroll
        for (int o = 16; o > 0; o >>= 1) m = fmaxf(m, __shfl_xor_sync(0xffffffffu, m, o));
        float e0 = (lane      < NC) ? __expf(x0 - m) : 0.f;
        float e1 = (lane + 32 < NC) ? __expf(x1 - m) : 0.f;
        float e2 = (lane + 64 < NC) ? __expf(x2 - m) : 0.f;
        float s = e0 + e1 + e2;
        #pragma unroll
        for (int o = 16; o > 0; o >>= 1) s += __shfl_xor_sync(0xffffffffu, s, o);
        float inv = __frcp_rn(s);
        if (lane      < NC) s_prob[qi][lane]      = e0 * inv;
        if (lane + 32 < NC) s_prob[qi][lane + 32] = e1 * inv;
        if (lane + 64 < NC) s_prob[qi][lane + 64] = e2 * inv;
    }
    if (tid < qlim) {
        const float* pb = pboxes + ((size_t)b * NQ + qbase + tid) * 4;
        float cx = pb[0], cy = pb[1], w = pb[2], h = pb[3];
        s_pba[tid] = make_float4(cx, cy, w, h);
        float x0 = cx - 0.5f * w, y0 = cy - 0.5f * h;
        float x1 = cx + 0.5f * w, y1 = cy + 0.5f * h;
        s_pbb[tid] = make_float4(x0, y0, x1, y1);
        s_parea[tid] = (x1 - x0) * (y1 - y0);
    }
    __syncthreads();

    const float4* tb4 = (const float4*)tboxes;
    float* outb = out + (size_t)b * NQ * NTT + (size_t)qbase * NTT;

    if (warp < 7) {
        const int j0 = warp * 128 + lane * 4;
        float4 tr[4]; float X0[4], Y0[4], X1[4], Y1[4], ar[4]; int lb[4];
        #pragma unroll
        for (int t = 0; t < 4; t++) {
            tr[t] = tb4[j0 + t];
            X0[t] = tr[t].x - 0.5f * tr[t].z; Y0[t] = tr[t].y - 0.5f * tr[t].w;
            X1[t] = tr[t].x + 0.5f * tr[t].z; Y1[t] = tr[t].y + 0.5f * tr[t].w;
            ar[t] = (X1[t] - X0[t]) * (Y1[t] - Y0[t]);
            lb[t] = tlabels[j0 + t];
        }
        #pragma unroll 2
        for (int qi = 0; qi < qlim; qi++) {
            float4 pa  = s_pba[qi];
            float4 pbx = s_pbb[qi];
            float parea = s_parea[qi];
            float4 r;
            r.x = cost_elem(pa, pbx, parea, s_prob[qi][lb[0]], tr[0], X0[0], Y0[0], X1[0], Y1[0], ar[0]);
            r.y = cost_elem(pa, pbx, parea, s_prob[qi][lb[1]], tr[1], X0[1], Y0[1], X1[1], Y1[1], ar[1]);
            r.z = cost_elem(pa, pbx, parea, s_prob[qi][lb[2]], tr[2], X0[2], Y0[2], X1[2], Y1[2], ar[2]);
            r.w = cost_elem(pa, pbx, parea, s_prob[qi][lb[3]], tr[3], X0[3], Y0[3], X1[3], Y1[3], ar[3]);
            __stcs((float4*)(outb + (size_t)qi * NTT + j0), r);
        }
    } else {
        const int j0 = 896 + lane * 2;
        float4 trA = tb4[j0], trB = tb4[j0 + 1];
        float aX0 = trA.x - 0.5f * trA.z, aY0 = trA.y - 0.5f * trA.w;
        float aX1 = trA.x + 0.5f * trA.z, aY1 = trA.y + 0.5f * trA.w;
        float areaA = (aX1 - aX0) * (aY1 - aY0);
        float bX0 = trB.x - 0.5f * trB.z, bY0 = trB.y - 0.5f * trB.w;
        float bX1 = trB.x + 0.5f * trB.z, bY1 = trB.y + 0.5f * trB.w;
        float areaB = (bX1 - bX0) * (bY1 - bY0);
        const int labA = tlabels[j0], labB = tlabels[j0 + 1];
        #pragma unroll 2
        for (int qi = 0; qi < qlim; qi++) {
            float4 pa  = s_pba[qi];
            float4 pbx = s_pbb[qi];
            float parea = s_parea[qi];
            float resA = cost_elem(pa, pbx, parea, s_prob[qi][labA], trA, aX0, aY0, aX1, aY1, areaA);
            float resB = cost_elem(pa, pbx, parea, s_prob[qi][labB], trB, bX0, bY0, bX1, bY1, areaB);
            __stcs((float2*)(outb + (size_t)qi * NTT + j0), make_float2(resA, resB));
        }
    }
}

// ---------------------------------------------------------------------------
// Kernel 2: self-contained per-batch solver. Computes its own 30x900 cost
// slice into SMEM (8 warps, unstabilized softmax — indices only), then
// runs the warp-JV with greedy row-min init. Releases cost_kernel at entry.
// ---------------------------------------------------------------------------
extern __shared__ float scst[];     // [NT][PITCH]

__global__ void __launch_bounds__(256) lsa_kernel(
    const float* __restrict__ logits,
    const float* __restrict__ pboxes,
    const int*   __restrict__ tlabels,
    const float* __restrict__ tboxes,
    float* __restrict__ out_pred,
    float* __restrict__ out_tgt)
{
    asm volatile("griddepcontrol.launch_dependents;");

    __shared__ float u_s[NT];
    __shared__ int   rarg_s[NT];
    __shared__ int   r4c[NQ];
    __shared__ int   c4r[NT];
    __shared__ int   path_s[NQ];
    __shared__ int   sc_s[NT + 1];
    __shared__ float scv_s[NT + 1];
    __shared__ int   free_s[NT];
    __shared__ int   nfree_s;

    const int bi   = blockIdx.x;
    const int tid  = threadIdx.x;
    const int warp = tid >> 5;
    const int lane = tid & 31;

    for (int j = tid; j < NQ; j += 256) r4c[j] = -1;
    if (tid < NT) c4r[tid] = -1;

    // ---- slice compute: warp w handles q = w, w+8, ... ----
    // per-lane target constants (lane < NT)
    float4 tr = make_float4(0, 0, 0, 0);
    float tX0 = 0, tY0 = 0, tX1 = 0, tY1 = 0, tarea = 0;
    int lab = 0;
    if (lane < NT) {
        tr = ((const float4*)tboxes)[bi * NT + lane];
        tX0 = tr.x - 0.5f * tr.z; tY0 = tr.y - 0.5f * tr.w;
        tX1 = tr.x + 0.5f * tr.z; tY1 = tr.y + 0.5f * tr.w;
        tarea = (tX1 - tX0) * (tY1 - tY0);
        lab = tlabels[bi * NT + lane];
    }
    const float* lgbase = logits + (size_t)bi * NQ * NC;
    const float4* pb4   = (const float4*)pboxes + (size_t)bi * NQ;

    for (int q = warp; q < NQ; q += 8) {
        const float* lg = lgbase + (size_t)q * NC;
        // unstabilized softmax denominator (indices-only precision)
        float e0 = __expf(lg[lane]);
        float e1 = (lane + 32 < NC) ? __expf(lg[lane + 32]) : 0.f;
        float e2 = (lane + 64 < NC) ? __expf(lg[lane + 64]) : 0.f;
        float s = e0 + e1 + e2;
        #pragma unroll
        for (int o = 16; o > 0; o >>= 1) s += __shfl_xor_sync(0xffffffffu, s, o);
        float inv = __frcp_rn(s);

        float4 pa = pb4[q];   // uniform -> broadcast LDG.128
        float px0 = pa.x - 0.5f * pa.z, py0 = pa.y - 0.5f * pa.w;
        float px1 = pa.x + 0.5f * pa.z, py1 = pa.y + 0.5f * pa.w;
        float4 pbx = make_float4(px0, py0, px1, py1);
        float parea = (px1 - px0) * (py1 - py0);

        if (lane < NT) {
            float prob = __expf(lg[lab]) * inv;
            float res = cost_elem(pa, pbx, parea, prob, tr, tX0, tY0, tX1, tY1, tarea);
            scst[lane * PITCH + q] = res;
        }
    }
    __syncthreads();

    // ---- row mins (8 warps) ----
    for (int t = warp; t < NT; t += 8) {
        const float* crow = scst + t * PITCH;
        unsigned long long best = ~0ull;
        #pragma unroll
        for (int k = 0; k < KLOC; k++) {
            int j = k * 32 + lane;
            if (j < NQ) {
                unsigned long long p = ((unsigned long long)fkey(crow[j]) << 32) | (unsigned)j;
                if (p < best) best = p;
            }
        }
        float mv; int mi;
        wargmin(best, &mv, &mi);
        if (lane == 0) { u_s[t] = mv; rarg_s[t] = mi; }
    }
    __syncthreads();
    if (tid >= 32) return;
    const int l = tid;

    if (l == 0) {
        int nf = 0;
        for (int t = 0; t < NT; t++) {
            int j = rarg_s[t];
            if (r4c[j] < 0) { r4c[j] = t; c4r[t] = j; }
            else free_s[nf++] = t;
        }
        nfree_s = nf;
    }
    __syncwarp();
    const int nfree = nfree_s;
    const unsigned fullmask = (l < 4) ? 0x1FFFFFFFu : 0x0FFFFFFFu;

    float v_r[KLOC];
    float spc_r[KLOC];
    #pragma unroll
    for (int k = 0; k < KLOC; k++) v_r[k] = 0.f;

    for (int fi = 0; fi < nfree; fi++) {
        const int cur = free_s[fi];
        unsigned rem = fullmask;
        #pragma unroll
        for (int k = 0; k < KLOC; k++) spc_r[k] = FINF;
        float minVal = 0.f;
        int i = cur, sink = -1, nSC = 0;

        while (true) {
            const float um = u_s[i];
            const float* crow = scst + i * PITCH;

            float c[KLOC];
            #pragma unroll
            for (int k = 0; k < KLOC; k++)
                c[k] = (k < 28 || l < 4) ? crow[k * 32 + l] : FINF;

            unsigned long long b0 = ~0ull, b1 = ~0ull, b2 = ~0ull, b3 = ~0ull;
            #pragma unroll
            for (int k = 0; k < KLOC; k++) {
                if ((rem >> k) & 1u) {
                    float r = minVal + (c[k] - um - v_r[k]);
                    if (r < spc_r[k]) { spc_r[k] = r; path_s[k * 32 + l] = i; }
                    unsigned long long p =
                        ((unsigned long long)fkey(spc_r[k]) << 32) | (unsigned)(k * 32 + l);
                    switch (k & 3) {
                        case 0: if (p < b0) b0 = p; break;
                        case 1: if (p < b1) b1 = p; break;
                        case 2: if (p < b2) b2 = p; break;
                        default: if (p < b3) b3 = p; break;
                    }
                }
            }
            unsigned long long best = b0;
            if (b1 < best) best = b1;
            if (b2 < best) best = b2;
            if (b3 < best) best = b3;

            int j1;
            wargmin(best, &minVal, &j1);
            const int r4 = r4c[j1];
            if (r4 < 0) { sink = j1; break; }
            if (l == (j1 & 31)) rem &= ~(1u << (j1 >> 5));
            if (l == 0) { sc_s[nSC] = j1; scv_s[nSC] = minVal; }
            nSC++;
            i = r4;
        }
        __syncwarp();

        if (l == 0) {
            u_s[cur] += minVal;
            for (int a = 0; a < nSC; a++) {
                int ir = r4c[sc_s[a]];
                u_s[ir] += minVal - scv_s[a];
            }
        }
        for (int a = 0; a < nSC; a++) {
            int j = sc_s[a];
            float d = minVal - scv_s[a];
            int kk = j >> 5, ll = j & 31;
            #pragma unroll
            for (int k = 0; k < KLOC; k++)
                if (k == kk && l == ll) v_r[k] -= d;
        }
        __syncwarp();

        if (l == 0) {
            int j = sink;
            while (true) {
                int ir = path_s[j];
                r4c[j] = ir;
                int tmp = c4r[ir];
                c4r[ir] = j;
                j = tmp;
                if (ir == cur) break;
            }
        }
        __syncwarp();
    }

    if (l == 0) {
        int ord[NT];
        for (int k = 0; k < NT; k++) ord[k] = k;
        for (int a = 1; a < NT; a++) {
            int key = ord[a]; int kv = c4r[key]; int b2i = a - 1;
            while (b2i >= 0 && c4r[ord[b2i]] > kv) { ord[b2i + 1] = ord[b2i]; b2i--; }
            ord[b2i + 1] = key;
        }
        for (int k = 0; k < NT; k++) {
            out_pred[bi * NT + k] = (float)c4r[ord[k]];
            out_tgt[bi * NT + k]  = (float)ord[k];
        }
    }
}

// ---------------------------------------------------------------------------
extern "C" void kernel_launch(void* const* d_in, const int* in_sizes, int n_in,
                              void* d_out, int out_size)
{
    const float* logits  = (const float*)d_in[0];
    const float* pboxes  = (const float*)d_in[1];
    const int*   tlabels = (const int*)d_in[2];
    const float* tboxes  = (const float*)d_in[3];
    float* out = (float*)d_out;
    float* out_pred = out + (size_t)BS * NQ * NTT;
    float* out_tgt  = out_pred + (size_t)BS * NT;

    const size_t lsa_smem = (size_t)NT * PITCH * sizeof(float);   // ~105.6 KB
    cudaFuncSetAttribute(lsa_kernel, cudaFuncAttributeMaxDynamicSharedMemorySize,
                         (int)lsa_smem);

    // 1) solver: 32 blocks, 1/SM; computes its own slice; releases dependents
    //    at entry so the cost kernel fills the remaining SMs immediately.
    lsa_kernel<<<BS, 256, lsa_smem>>>(logits, pboxes, tlabels, tboxes,
                                      out_pred, out_tgt);

    // 2) cost matrix as PDL secondary — runs concurrently with the solver.
    {
        cudaLaunchConfig_t cfg = {};
        cfg.gridDim  = dim3(QCHUNKS, BS);
        cfg.blockDim = dim3(256, 1, 1);
        cfg.stream = 0;
        cudaLaunchAttribute attr;
        attr.id = cudaLaunchAttributeProgrammaticStreamSerialization;
        attr.val.programmaticStreamSerializationAllowed = 1;
        cfg.attrs = &attr;
        cfg.numAttrs = 1;
        cudaLaunchKernelEx(&cfg, cost_kernel, logits, pboxes, tlabels, tboxes, out);
    }
}

// round 13
// speedup vs baseline: 1.5986x; 1.5986x over previous
#include <cuda_runtime.h>
#include <math.h>
#include <stdint.h>

#define BS 32
#define NQ 900
#define NC 91
#define NT 30
#define NTT (BS * NT)   // 960
#define QPB 32
#define QCHUNKS 29      // ceil(NQ/QPB)
#define KLOC 29
#define FINF 3.0e38f

__device__ float g_diag[BS * NT * NQ];   // [b][t][q]
__device__ int   g_cnt[BS];              // per-batch diag completion counters

__device__ __forceinline__ unsigned fkey(float f) {
    unsigned b = __float_as_uint(f);
    return (b & 0x80000000u) ? ~b : (b | 0x80000000u);
}
__device__ __forceinline__ float funkey(unsigned k) {
    unsigned b = (k & 0x80000000u) ? (k & 0x7FFFFFFFu) : ~k;
    return __uint_as_float(b);
}

__device__ __forceinline__ void wargmin(unsigned long long best, float* val, int* idx) {
    unsigned key  = (unsigned)(best >> 32);
    unsigned wmin = __reduce_min_sync(0xffffffffu, key);
    unsigned cand = (key == wmin) ? (unsigned)(best & 0xFFFFFFFFu) : 0xFFFFFFFFu;
    unsigned widx = __reduce_min_sync(0xffffffffu, cand);
    *val = funkey(wmin);
    *idx = (int)widx;
}

// ---------------------------------------------------------------------------
__global__ void reset_kernel() {
    if (threadIdx.x < BS) g_cnt[threadIdx.x] = 0;
}

// ---------------------------------------------------------------------------
// one q's softmax into dst[92] (warp-collective). lane/lane+32 always < 91.
// ---------------------------------------------------------------------------
__device__ __forceinline__ void softmax_one(
    const float* __restrict__ lg, int lane, float* __restrict__ dst)
{
    float x0 = lg[lane];
    float x1 = lg[lane + 32];
    float x2 = (lane + 64 < NC) ? lg[lane + 64] : -FINF;
    float m = fmaxf(x0, fmaxf(x1, x2));
    #pragma unroll
    for (int o = 16; o > 0; o >>= 1) m = fmaxf(m, __shfl_xor_sync(0xffffffffu, m, o));
    float e0 = __expf(x0 - m);
    float e1 = __expf(x1 - m);
    float e2 = (lane + 64 < NC) ? __expf(x2 - m) : 0.f;
    float s = e0 + e1 + e2;
    #pragma unroll
    for (int o = 16; o > 0; o >>= 1) s += __shfl_xor_sync(0xffffffffu, s, o);
    float inv = __frcp_rn(s);
    dst[lane]      = e0 * inv;
    dst[lane + 32] = e1 * inv;
    if (lane + 64 < NC) dst[lane + 64] = e2 * inv;
}

__device__ __forceinline__ void phase1(
    const float* __restrict__ logits, const float* __restrict__ pboxes,
    int b, int qbase, int qlim, int tid, int warp, int lane,
    float (*s_prob)[92], float4* s_pba, float4* s_pbb, float* s_parea)
{
    const float* lgb = logits + ((size_t)b * NQ + qbase) * NC;
    if (qlim == QPB) {
        // compile-time trip count -> pipelined LDG/exp chains
        #pragma unroll
        for (int r = 0; r < QPB / 8; r++) {
            int qi = warp + r * 8;
            softmax_one(lgb + (size_t)qi * NC, lane, s_prob[qi]);
        }
    } else {
        for (int qi = warp; qi < qlim; qi += 8)
            softmax_one(lgb + (size_t)qi * NC, lane, s_prob[qi]);
    }
    if (tid < qlim) {
        const float* pb = pboxes + ((size_t)b * NQ + qbase + tid) * 4;
        float cx = pb[0], cy = pb[1], w = pb[2], h = pb[3];
        s_pba[tid] = make_float4(cx, cy, w, h);
        float x0 = cx - 0.5f * w, y0 = cy - 0.5f * h;
        float x1 = cx + 0.5f * w, y1 = cy + 0.5f * h;
        s_pbb[tid] = make_float4(x0, y0, x1, y1);
        s_parea[tid] = (x1 - x0) * (y1 - y0);
    }
}

// min/max symmetry: encl extent = (pw+tw) - raw_intersection_extent
__device__ __forceinline__ float cost_elem(
    float4 pa, float4 pbx, float parea, float prob,
    float4 tr, float tX0, float tY0, float tX1, float tY1, float tarea)
{
    float cb = fabsf(pa.x - tr.x) + fabsf(pa.y - tr.y)
             + fabsf(pa.z - tr.z) + fabsf(pa.w - tr.w);
    float rw = fminf(pbx.z, tX1) - fmaxf(pbx.x, tX0);
    float rh = fminf(pbx.w, tY1) - fmaxf(pbx.y, tY0);
    float inter = fmaxf(rw, 0.f) * fmaxf(rh, 0.f);
    float uni = parea + tarea - inter;
    float ew = (pa.z + tr.z) - rw;
    float eh = (pa.w + tr.w) - rh;
    float encl = ew * eh;
    float num = 2.0f * fmaf(inter, encl, uni * uni);
    return fmaf(5.0f, cb, 5.0f) - prob - __fdividef(num, uni * encl);
}

// ---------------------------------------------------------------------------
// Kernel 0: diagonal slices -> g_diag; releases dependents at entry,
// signals per-batch completion.
// ---------------------------------------------------------------------------
__global__ void __launch_bounds__(256) diag_kernel(
    const float* __restrict__ logits,
    const float* __restrict__ pboxes,
    const int*   __restrict__ tlabels,
    const float* __restrict__ tboxes)
{
    asm volatile("griddepcontrol.launch_dependents;");

    __shared__ float  s_prob[QPB][92];
    __shared__ float4 s_pba[QPB];
    __shared__ float4 s_pbb[QPB];
    __shared__ float  s_parea[QPB];

    const int b     = blockIdx.y;
    const int qbase = blockIdx.x * QPB;
    const int tid   = threadIdx.x;
    const int warp  = tid >> 5;
    const int lane  = tid & 31;
    const int qlim  = min(QPB, NQ - qbase);

    phase1(logits, pboxes, b, qbase, qlim, tid, warp, lane,
           s_prob, s_pba, s_pbb, s_parea);
    __syncthreads();

    float4 tr = make_float4(0, 0, 0, 0);
    float tX0 = 0, tY0 = 0, tX1 = 0, tY1 = 0, tarea = 0;
    int lab = 0;
    if (lane < NT) {
        tr = ((const float4*)tboxes)[b * NT + lane];
        tX0 = tr.x - 0.5f * tr.z; tY0 = tr.y - 0.5f * tr.w;
        tX1 = tr.x + 0.5f * tr.z; tY1 = tr.y + 0.5f * tr.w;
        tarea = (tX1 - tX0) * (tY1 - tY0);
        lab = tlabels[b * NT + lane];
    }
    float* gout = g_diag + (size_t)b * NT * NQ + qbase;
    if (qlim == QPB) {
        #pragma unroll
        for (int r = 0; r < QPB / 8; r++) {
            int qi = warp + r * 8;
            if (lane < NT) {
                float res = cost_elem(s_pba[qi], s_pbb[qi], s_parea[qi],
                                      s_prob[qi][lab], tr, tX0, tY0, tX1, tY1, tarea);
                gout[(size_t)lane * NQ + qi] = res;
            }
        }
    } else {
        for (int qi = warp; qi < qlim; qi += 8) {
            if (lane < NT) {
                float res = cost_elem(s_pba[qi], s_pbb[qi], s_parea[qi],
                                      s_prob[qi][lab], tr, tX0, tY0, tX1, tY1, tarea);
                gout[(size_t)lane * NQ + qi] = res;
            }
        }
    }

    __threadfence();
    __syncthreads();
    if (tid == 0) atomicAdd(&g_cnt[b], 1);
}

// ---------------------------------------------------------------------------
// Kernel 1: full cost matrix. Lane owns 4 targets (STG.128 streaming),
// warp 7 covers the 64-target tail with float2.
// ---------------------------------------------------------------------------
__global__ void __launch_bounds__(256) cost_kernel(
    const float* __restrict__ logits,
    const float* __restrict__ pboxes,
    const int*   __restrict__ tlabels,
    const float* __restrict__ tboxes,
    float* __restrict__ out)
{
    __shared__ float  s_prob[QPB][92];
    __shared__ float4 s_pba[QPB];
    __shared__ float4 s_pbb[QPB];
    __shared__ float  s_parea[QPB];

    const int b     = blockIdx.y;
    const int qbase = blockIdx.x * QPB;
    const int tid   = threadIdx.x;
    const int warp  = tid >> 5;
    const int lane  = tid & 31;
    const int qlim  = min(QPB, NQ - qbase);

    phase1(logits, pboxes, b, qbase, qlim, tid, warp, lane,
           s_prob, s_pba, s_pbb, s_parea);
    __syncthreads();

    const float4* tb4 = (const float4*)tboxes;
    float* outb = out + (size_t)b * NQ * NTT + (size_t)qbase * NTT;

    if (warp < 7) {
        const int j0 = warp * 128 + lane * 4;
        float4 tr[4]; float X0[4], Y0[4], X1[4], Y1[4], ar[4]; int lb[4];
        #pragma unroll
        for (int t = 0; t < 4; t++) {
            tr[t] = tb4[j0 + t];
            X0[t] = tr[t].x - 0.5f * tr[t].z; Y0[t] = tr[t].y - 0.5f * tr[t].w;
            X1[t] = tr[t].x + 0.5f * tr[t].z; Y1[t] = tr[t].y + 0.5f * tr[t].w;
            ar[t] = (X1[t] - X0[t]) * (Y1[t] - Y0[t]);
            lb[t] = tlabels[j0 + t];
        }
        auto body = [&](int qi) {
            float4 pa  = s_pba[qi];
            float4 pbx = s_pbb[qi];
            float parea = s_parea[qi];
            float4 r;
            r.x = cost_elem(pa, pbx, parea, s_prob[qi][lb[0]], tr[0], X0[0], Y0[0], X1[0], Y1[0], ar[0]);
            r.y = cost_elem(pa, pbx, parea, s_prob[qi][lb[1]], tr[1], X0[1], Y0[1], X1[1], Y1[1], ar[1]);
            r.z = cost_elem(pa, pbx, parea, s_prob[qi][lb[2]], tr[2], X0[2], Y0[2], X1[2], Y1[2], ar[2]);
            r.w = cost_elem(pa, pbx, parea, s_prob[qi][lb[3]], tr[3], X0[3], Y0[3], X1[3], Y1[3], ar[3]);
            __stcs((float4*)(outb + (size_t)qi * NTT + j0), r);
        };
        if (qlim == QPB) {
            #pragma unroll 2
            for (int qi = 0; qi < QPB; qi++) body(qi);
        } else {
            for (int qi = 0; qi < qlim; qi++) body(qi);
        }
    } else {
        const int j0 = 896 + lane * 2;
        float4 trA = tb4[j0], trB = tb4[j0 + 1];
        float aX0 = trA.x - 0.5f * trA.z, aY0 = trA.y - 0.5f * trA.w;
        float aX1 = trA.x + 0.5f * trA.z, aY1 = trA.y + 0.5f * trA.w;
        float areaA = (aX1 - aX0) * (aY1 - aY0);
        float bX0 = trB.x - 0.5f * trB.z, bY0 = trB.y - 0.5f * trB.w;
        float bX1 = trB.x + 0.5f * trB.z, bY1 = trB.y + 0.5f * trB.w;
        float areaB = (bX1 - bX0) * (bY1 - bY0);
        const int labA = tlabels[j0], labB = tlabels[j0 + 1];
        auto body = [&](int qi) {
            float4 pa  = s_pba[qi];
            float4 pbx = s_pbb[qi];
            float parea = s_parea[qi];
            float resA = cost_elem(pa, pbx, parea, s_prob[qi][labA], trA, aX0, aY0, aX1, aY1, areaA);
            float resB = cost_elem(pa, pbx, parea, s_prob[qi][labB], trB, bX0, bY0, bX1, bY1, areaB);
            __stcs((float2*)(outb + (size_t)qi * NTT + j0), make_float2(resA, resB));
        };
        if (qlim == QPB) {
            #pragma unroll 4
            for (int qi = 0; qi < QPB; qi++) body(qi);
        } else {
            for (int qi = 0; qi < qlim; qi++) body(qi);
        }
    }
}

// ---------------------------------------------------------------------------
// Kernel 2: warp-per-problem exact JV (unchanged from R8). Launches early
// (PSS), spins on its batch's diag counter, solves from L2/L1-hot g_diag.
// ---------------------------------------------------------------------------
__global__ void __launch_bounds__(256) lsa_kernel(
    float* __restrict__ out_pred,
    float* __restrict__ out_tgt)
{
    asm volatile("griddepcontrol.launch_dependents;");

    __shared__ float u_s[NT];
    __shared__ int   rarg_s[NT];
    __shared__ int   r4c[NQ];
    __shared__ int   c4r[NT];
    __shared__ int   path_s[NQ];
    __shared__ int   sc_s[NT + 1];
    __shared__ float scv_s[NT + 1];
    __shared__ int   free_s[NT];
    __shared__ int   nfree_s;

    const int bi  = blockIdx.x;
    const int tid = threadIdx.x;
    const float* dslice = g_diag + (size_t)bi * NT * NQ;

    for (int j = tid; j < NQ; j += 256) r4c[j] = -1;
    if (tid < NT) c4r[tid] = -1;

    if (tid == 0) {
        while (atomicAdd(&g_cnt[bi], 0) < QCHUNKS) { }
        __threadfence();
    }
    __syncthreads();

    {
        const int w = tid >> 5, ln = tid & 31;
        for (int t = w; t < NT; t += 8) {
            const float* crow = dslice + t * NQ;
            unsigned long long best = ~0ull;
            #pragma unroll
            for (int k = 0; k < KLOC; k++) {
                int j = k * 32 + ln;
                if (j < NQ) {
                    unsigned long long p = ((unsigned long long)fkey(crow[j]) << 32) | (unsigned)j;
                    if (p < best) best = p;
                }
            }
            float mv; int mi;
            wargmin(best, &mv, &mi);
            if (ln == 0) { u_s[t] = mv; rarg_s[t] = mi; }
        }
    }
    __syncthreads();
    if (tid >= 32) return;
    const int l = tid;

    if (l == 0) {
        int nf = 0;
        for (int t = 0; t < NT; t++) {
            int j = rarg_s[t];
            if (r4c[j] < 0) { r4c[j] = t; c4r[t] = j; }
            else free_s[nf++] = t;
        }
        nfree_s = nf;
    }
    __syncwarp();
    const int nfree = nfree_s;
    const unsigned fullmask = (l < 4) ? 0x1FFFFFFFu : 0x0FFFFFFFu;

    float v_r[KLOC];
    float spc_r[KLOC];
    #pragma unroll
    for (int k = 0; k < KLOC; k++) v_r[k] = 0.f;

    for (int fi = 0; fi < nfree; fi++) {
        const int cur = free_s[fi];
        unsigned rem = fullmask;
        #pragma unroll
        for (int k = 0; k < KLOC; k++) spc_r[k] = FINF;
        float minVal = 0.f;
        int i = cur, sink = -1, nSC = 0;

        while (true) {
            const float um = u_s[i];
            const float* crow = dslice + i * NQ;

            float c[KLOC];
            #pragma unroll
            for (int k = 0; k < KLOC; k++)
                c[k] = (k < 28 || l < 4) ? crow[k * 32 + l] : FINF;

            unsigned long long b0 = ~0ull, b1 = ~0ull, b2 = ~0ull, b3 = ~0ull;
            #pragma unroll
            for (int k = 0; k < KLOC; k++) {
                if ((rem >> k) & 1u) {
                    float r = minVal + (c[k] - um - v_r[k]);
                    if (r < spc_r[k]) { spc_r[k] = r; path_s[k * 32 + l] = i; }
                    unsigned long long p =
                        ((unsigned long long)fkey(spc_r[k]) << 32) | (unsigned)(k * 32 + l);
                    switch (k & 3) {
                        case 0: if (p < b0) b0 = p; break;
                        case 1: if (p < b1) b1 = p; break;
                        case 2: if (p < b2) b2 = p; break;
                        default: if (p < b3) b3 = p; break;
                    }
                }
            }
            unsigned long long best = b0;
            if (b1 < best) best = b1;
            if (b2 < best) best = b2;
            if (b3 < best) best = b3;

            int j1;
            wargmin(best, &minVal, &j1);
            const int r4 = r4c[j1];
            if (r4 < 0) { sink = j1; break; }
            if (l == (j1 & 31)) rem &= ~(1u << (j1 >> 5));
            if (l == 0) { sc_s[nSC] = j1; scv_s[nSC] = minVal; }
            nSC++;
            i = r4;
        }
        __syncwarp();

        if (l == 0) {
            u_s[cur] += minVal;
            for (int a = 0; a < nSC; a++) {
                int ir = r4c[sc_s[a]];
                u_s[ir] += minVal - scv_s[a];
            }
        }
        for (int a = 0; a < nSC; a++) {
            int j = sc_s[a];
            float d = minVal - scv_s[a];
            int kk = j >> 5, ll = j & 31;
            #pragma unroll
            for (int k = 0; k < KLOC; k++)
                if (k == kk && l == ll) v_r[k] -= d;
        }
        __syncwarp();

        if (l == 0) {
            int j = sink;
            while (true) {
                int ir = path_s[j];
                r4c[j] = ir;
                int tmp = c4r[ir];
                c4r[ir] = j;
                j = tmp;
                if (ir == cur) break;
            }
        }
        __syncwarp();
    }

    if (l == 0) {
        int ord[NT];
        for (int k = 0; k < NT; k++) ord[k] = k;
        for (int a = 1; a < NT; a++) {
            int key = ord[a]; int kv = c4r[key]; int b2i = a - 1;
            while (b2i >= 0 && c4r[ord[b2i]] > kv) { ord[b2i + 1] = ord[b2i]; b2i--; }
            ord[b2i + 1] = key;
        }
        for (int k = 0; k < NT; k++) {
            out_pred[bi * NT + k] = (float)c4r[ord[k]];
            out_tgt[bi * NT + k]  = (float)ord[k];
        }
    }
}

// ---------------------------------------------------------------------------
extern "C" void kernel_launch(void* const* d_in, const int* in_sizes, int n_in,
                              void* d_out, int out_size)
{
    const float* logits  = (const float*)d_in[0];
    const float* pboxes  = (const float*)d_in[1];
    const int*   tlabels = (const int*)d_in[2];
    const float* tboxes  = (const float*)d_in[3];
    float* out = (float*)d_out;
    float* out_pred = out + (size_t)BS * NQ * NTT;
    float* out_tgt  = out_pred + (size_t)BS * NT;

    dim3 grid(QCHUNKS, BS);

    reset_kernel<<<1, 32>>>();

    diag_kernel<<<grid, 256>>>(logits, pboxes, tlabels, tboxes);

    cudaLaunchAttribute attr;
    attr.id = cudaLaunchAttributeProgrammaticStreamSerialization;
    attr.val.programmaticStreamSerializationAllowed = 1;

    {
        cudaLaunchConfig_t cfg = {};
        cfg.gridDim = dim3(BS, 1, 1);
        cfg.blockDim = dim3(256, 1, 1);
        cfg.stream = 0;
        cfg.attrs = &attr;
        cfg.numAttrs = 1;
        cudaLaunchKernelEx(&cfg, lsa_kernel, out_pred, out_tgt);
    }

    {
        cudaLaunchConfig_t cfg = {};
        cfg.gridDim = grid;
        cfg.blockDim = dim3(256, 1, 1);
        cfg.stream = 0;
        cfg.attrs = &attr;
        cfg.numAttrs = 1;
        cudaLaunchKernelEx(&cfg, cost_kernel, logits, pboxes, tlabels, tboxes, out);
    }
}